// round 16
// baseline (speedup 1.0000x reference)
#include <cuda_runtime.h>
#include <cuda_bf16.h>
#include <cstdint>

#define NN    100000
#define NE    1600000
#define DD    128
#define NG    128
#define DOUT  64
#define NBLK  98          // ceil(NN / 1024)
#define NTILE 782         // ceil(NN / 128)

#define APAD  8
#define AK    (DD + APAD)                    // 136 bf16 per row
#define SMEMB (3 * 128 * AK * 2)             // As + Bh + Bl = 104448 B

// ---------------- scratch (device globals: allocation-free) ----------------
__device__ __align__(16) __nv_bfloat16 g_hb[(size_t)NN * DD]; // h = xW (UNSCALED), bf16
__device__ __align__(16) __nv_bfloat16 g_xb[(size_t)NN * DD]; // layer output, bf16
__device__ __align__(16) __nv_bfloat16 g_wsw[3 * 32768];      // W^T split hi+lo, 3 layers
__device__ float g_dinv[NN];
__device__ int   g_indeg[NN];
__device__ int   g_off  [NN];
__device__ int   g_cur  [NN];
__device__ int   g_srcl [NE];
__device__ int   g_bsum [NBLK];
__device__ int   g_bbase[NBLK];
__device__ int   g_cnti [NG];
__device__ int   g_gstart[NG + 1];
__device__ float g_pool [NG * DD];

// ---------------- mma/ldmatrix helpers --------------------------------------
__device__ __forceinline__ uint32_t smem_u32(const void* p) {
    uint32_t a;
    asm("{ .reg .u64 t; cvta.to.shared.u64 t, %1; cvt.u32.u64 %0, t; }"
        : "=r"(a) : "l"(p));
    return a;
}
__device__ __forceinline__ void ldsm_x4(uint32_t (&r)[4], uint32_t addr) {
    asm volatile("ldmatrix.sync.aligned.m8n8.x4.shared.b16 {%0,%1,%2,%3}, [%4];"
                 : "=r"(r[0]), "=r"(r[1]), "=r"(r[2]), "=r"(r[3]) : "r"(addr));
}
__device__ __forceinline__ void mma_16816(float (&c)[4], const uint32_t (&a)[4],
                                          uint32_t b0, uint32_t b1) {
    asm volatile("mma.sync.aligned.m16n8k16.row.col.f32.bf16.bf16.f32 "
                 "{%0,%1,%2,%3}, {%4,%5,%6,%7}, {%8,%9}, {%0,%1,%2,%3};"
                 : "+f"(c[0]), "+f"(c[1]), "+f"(c[2]), "+f"(c[3])
                 : "r"(a[0]), "r"(a[1]), "r"(a[2]), "r"(a[3]), "r"(b0), "r"(b1));
}

// ---------------- init ------------------------------------------------------
__global__ void init_kernel() {
    int i = blockIdx.x * blockDim.x + threadIdx.x;
    if (i < NN) { g_indeg[i] = 0; g_cur[i] = 0; }
    if (i < NG) g_cnti[i] = 0;
}

// ---------------- in-degree histogram over dst (int4: 4 edges/thread) -------
__global__ void deg_kernel(const int* dst) {
    int i = blockIdx.x * blockDim.x + threadIdx.x;
    if (i < NE / 4) {
        int4 d4 = ((const int4*)dst)[i];
        if ((unsigned)d4.x < NN) atomicAdd(&g_indeg[d4.x], 1);
        if ((unsigned)d4.y < NN) atomicAdd(&g_indeg[d4.y], 1);
        if ((unsigned)d4.z < NN) atomicAdd(&g_indeg[d4.z], 1);
        if ((unsigned)d4.w < NN) atomicAdd(&g_indeg[d4.w], 1);
    }
}

// ---------------- dinv + per-graph node counts ------------------------------
__global__ void node_kernel(const int* batch) {
    int i = blockIdx.x * blockDim.x + threadIdx.x;
    if (i < NN) {
        g_dinv[i] = rsqrtf(1.0f + (float)g_indeg[i]);
        unsigned b = (unsigned)batch[i];
        if (b < NG) atomicAdd(&g_cnti[b], 1);
    }
}

// ---------------- scan A ----------------------------------------------------
__global__ void scanA_kernel() {
    __shared__ int sh[128];
    int b = blockIdx.x, t = threadIdx.x;
    int base = b * 1024 + t * 8;
    int s = 0;
#pragma unroll
    for (int j = 0; j < 8; j++) {
        int idx = base + j;
        if (idx < NN) s += g_indeg[idx];
    }
    sh[t] = s;
    __syncthreads();
    for (int off = 64; off > 0; off >>= 1) {
        if (t < off) sh[t] += sh[t + off];
        __syncthreads();
    }
    if (t == 0) g_bsum[b] = sh[0];
}

// ---------------- scan B ----------------------------------------------------
__global__ void scanB_kernel() {
    __shared__ int ts[128];
    int t = threadIdx.x;
    int v = (t < NBLK) ? g_bsum[t] : 0;
    ts[t] = v;
    __syncthreads();
    for (int off = 1; off < 128; off <<= 1) {
        int xv = (t >= off) ? ts[t - off] : 0;
        __syncthreads();
        ts[t] += xv;
        __syncthreads();
    }
    if (t < NBLK) g_bbase[t] = ts[t] - v;
    __syncthreads();
    int c = g_cnti[t];
    ts[t] = c;
    __syncthreads();
    for (int off = 1; off < 128; off <<= 1) {
        int xv = (t >= off) ? ts[t - off] : 0;
        __syncthreads();
        ts[t] += xv;
        __syncthreads();
    }
    g_gstart[t] = ts[t] - c;
    if (t == 127) g_gstart[128] = ts[127];
}

// ---------------- scan C ----------------------------------------------------
__global__ void scanC_kernel() {
    __shared__ int ts[128];
    int b = blockIdx.x, t = threadIdx.x;
    int base = b * 1024 + t * 8;
    int e[8];
    int s = 0;
#pragma unroll
    for (int j = 0; j < 8; j++) {
        int idx = base + j;
        int v = (idx < NN) ? g_indeg[idx] : 0;
        e[j] = s;
        s += v;
    }
    ts[t] = s;
    __syncthreads();
    for (int off = 1; off < 128; off <<= 1) {
        int xv = (t >= off) ? ts[t - off] : 0;
        __syncthreads();
        ts[t] += xv;
        __syncthreads();
    }
    int tbase = g_bbase[b] + (t > 0 ? ts[t - 1] : 0);
#pragma unroll
    for (int j = 0; j < 8; j++) {
        int idx = base + j;
        if (idx < NN) g_off[idx] = tbase + e[j];
    }
}

// ---------------- placement -------------------------------------------------
__global__ void place_kernel(const int* src, const int* dst) {
    int e = blockIdx.x * blockDim.x + threadIdx.x;
    if (e >= NE) return;
    unsigned d = (unsigned)dst[e];
    unsigned s = (unsigned)src[e];
    if (d < NN && s < NN) {
        int p = g_off[d] + atomicAdd(&g_cur[d], 1);
        g_srcl[p] = (int)s;
    }
}

// ---------------- W prep: W^T split into hi+lo bf16 -------------------------
__global__ void wprep_kernel(const float* W, int layer) {
    int id = blockIdx.x * blockDim.x + threadIdx.x;   // 16384 = 128n * 128k
    if (id >= 16384) return;
    int k = id & 127, n = id >> 7;
    float w = W[(size_t)k * DD + n];
    __nv_bfloat16 hi = __float2bfloat16(w);
    __nv_bfloat16 lo = __float2bfloat16(w - __bfloat162float(hi));
    g_wsw[layer * 32768 + id]         = hi;
    g_wsw[layer * 32768 + 16384 + id] = lo;
}

// ---------------- mma.sync GEMM: h = bf16(A @ W) (no dinv scaling) ----------
template <int USE_GX>
__global__ __launch_bounds__(256)
void gemm_mma_kernel(const float* A_ext, int layer) {
    extern __shared__ char smc[];
    __nv_bfloat16* As = (__nv_bfloat16*)smc;            // [128][AK]

    int t = threadIdx.x;
    int lane = t & 31, wid = t >> 5;
    int warp_m = wid & 3, warp_n = wid >> 2;
    int base = blockIdx.x * 128;

    // ---- stage A tile ----
    if (USE_GX) {
#pragma unroll
        for (int it = 0; it < 8; it++) {
            int j = it * 256 + t;          // 2048 uint4
            int row = j >> 4, seg = j & 15;
            int grow = base + row;
            uint4 v = make_uint4(0, 0, 0, 0);
            if (grow < NN)
                v = *(const uint4*)(g_xb + (size_t)grow * DD + seg * 8);
            *(uint4*)&As[row * AK + seg * 8] = v;
        }
    } else {
#pragma unroll
        for (int it = 0; it < 16; it++) {
            int j = it * 256 + t;          // 4096 float4
            int row = j >> 5, c4 = j & 31;
            int grow = base + row;
            float4 v = make_float4(0.f, 0.f, 0.f, 0.f);
            if (grow < NN)
                v = *(const float4*)(A_ext + (size_t)grow * DD + c4 * 4);
            __nv_bfloat162 p0 = __floats2bfloat162_rn(v.x, v.y);
            __nv_bfloat162 p1 = __floats2bfloat162_rn(v.z, v.w);
            uint2 u = make_uint2(*(unsigned*)&p0, *(unsigned*)&p1);
            *(uint2*)&As[row * AK + c4 * 4] = u;
        }
    }
    // ---- stage B tiles ----
    {
        const uint4* wsrc = (const uint4*)(g_wsw + layer * 32768);
#pragma unroll
        for (int it = 0; it < 16; it++) {
            int j = it * 256 + t;          // 4096 uint4 over both parts
            int part = j >> 11;
            int idx = j & 2047;
            int n = idx >> 4, seg = idx & 15;
            uint4 v = wsrc[j];
            __nv_bfloat16* Bp = As + 128 * AK + part * 128 * AK;
            *(uint4*)&Bp[n * AK + seg * 8] = v;
        }
    }
    __syncthreads();

    // ---- mainloop ----
    float acc[2][8][4];
#pragma unroll
    for (int i = 0; i < 2; i++)
#pragma unroll
        for (int j = 0; j < 8; j++)
#pragma unroll
            for (int q = 0; q < 4; q++) acc[i][j][q] = 0.f;

    uint32_t smb = smem_u32(As);
#pragma unroll
    for (int ks = 0; ks < 8; ks++) {
        uint32_t a[2][4];
#pragma unroll
        for (int i = 0; i < 2; i++) {
            int row = warp_m * 32 + i * 16 + (lane & 15);
            int kof = ks * 16 + (lane >> 4) * 8;
            ldsm_x4(a[i], smb + (row * AK + kof) * 2);
        }
#pragma unroll
        for (int part = 0; part < 2; part++) {
            uint32_t boff = (uint32_t)((128 * AK + part * 128 * AK) * 2);
#pragma unroll
            for (int j2 = 0; j2 < 4; j2++) {
                uint32_t b[4];
                int g = lane >> 3;
                int n = warp_n * 64 + j2 * 16 + (g >> 1) * 8 + (lane & 7);
                int kof = ks * 16 + (g & 1) * 8;
                ldsm_x4(b, smb + boff + (n * AK + kof) * 2);
#pragma unroll
                for (int i = 0; i < 2; i++) {
                    mma_16816(acc[i][2 * j2 + 0], a[i], b[0], b[1]);
                    mma_16816(acc[i][2 * j2 + 1], a[i], b[2], b[3]);
                }
            }
        }
    }

    // ---- epilogue: pack bf16x2 (no scaling) ----
#pragma unroll
    for (int i = 0; i < 2; i++) {
        int r0 = base + warp_m * 32 + i * 16 + (lane >> 2);
        int r1 = r0 + 8;
#pragma unroll
        for (int j = 0; j < 8; j++) {
            int col = warp_n * 64 + j * 8 + (lane & 3) * 2;
            if (r0 < NN) {
                __nv_bfloat162 p = __floats2bfloat162_rn(acc[i][j][0], acc[i][j][1]);
                *(unsigned*)(g_hb + (size_t)r0 * DD + col) = *(unsigned*)&p;
            }
            if (r1 < NN) {
                __nv_bfloat162 p = __floats2bfloat162_rn(acc[i][j][2], acc[i][j][3]);
                *(unsigned*)(g_hb + (size_t)r1 * DD + col) = *(unsigned*)&p;
            }
        }
    }
}

// ------- gather: xb[d] = bf16(relu(dinv[d]*(dinv[d]h[d]+Σ dinv[s]h[s])+b)) --
__global__ void gather_kernel(const float* bvec) {
    __shared__ int   s_idx[8][32];
    __shared__ float s_dv [8][32];
    int warp = threadIdx.x >> 5, lane = threadIdx.x & 31;
    int node = blockIdx.x * 8 + warp;
    if (node >= NN) return;

    int start = g_off[node];
    int cnt   = g_indeg[node];
    int half  = lane >> 4;
    int l16   = lane & 15;
    float dv  = g_dinv[node];

    float acc[8];
#pragma unroll
    for (int k = 0; k < 8; k++) acc[k] = 0.0f;

    // self-loop term: dinv[d] * h[d]
    if (half == 0) {
        uint4 v = *(const uint4*)(g_hb + (size_t)node * DD + l16 * 8);
        float2 f0 = __bfloat1622float2(*(__nv_bfloat162*)&v.x);
        float2 f1 = __bfloat1622float2(*(__nv_bfloat162*)&v.y);
        float2 f2 = __bfloat1622float2(*(__nv_bfloat162*)&v.z);
        float2 f3 = __bfloat1622float2(*(__nv_bfloat162*)&v.w);
        acc[0] = f0.x * dv; acc[1] = f0.y * dv; acc[2] = f1.x * dv; acc[3] = f1.y * dv;
        acc[4] = f2.x * dv; acc[5] = f2.y * dv; acc[6] = f3.x * dv; acc[7] = f3.y * dv;
    }

    for (int c = 0; c < cnt; c += 32) {
        int rem = cnt - c;
        if (rem > 32) rem = 32;
        if (lane < rem) {
            int s = g_srcl[start + c + lane];
            s_idx[warp][lane] = s;
            s_dv [warp][lane] = g_dinv[s];
        }
        __syncwarp();
#pragma unroll 4
        for (int j = half; j < rem; j += 2) {
            int s = s_idx[warp][j];
            float w = s_dv[warp][j];
            uint4 v = *(const uint4*)(g_hb + (size_t)s * DD + l16 * 8);
            float2 f0 = __bfloat1622float2(*(__nv_bfloat162*)&v.x);
            float2 f1 = __bfloat1622float2(*(__nv_bfloat162*)&v.y);
            float2 f2 = __bfloat1622float2(*(__nv_bfloat162*)&v.z);
            float2 f3 = __bfloat1622float2(*(__nv_bfloat162*)&v.w);
            acc[0] = fmaf(f0.x, w, acc[0]); acc[1] = fmaf(f0.y, w, acc[1]);
            acc[2] = fmaf(f1.x, w, acc[2]); acc[3] = fmaf(f1.y, w, acc[3]);
            acc[4] = fmaf(f2.x, w, acc[4]); acc[5] = fmaf(f2.y, w, acc[5]);
            acc[6] = fmaf(f3.x, w, acc[6]); acc[7] = fmaf(f3.y, w, acc[7]);
        }
        __syncwarp();
    }

#pragma unroll
    for (int k = 0; k < 8; k++)
        acc[k] += __shfl_xor_sync(0xffffffffu, acc[k], 16);

    int colbase = l16 * 8 + half * 4;
    int abase = half * 4;
    float o0 = fmaxf(fmaf(dv, acc[abase + 0], bvec[colbase + 0]), 0.f);
    float o1 = fmaxf(fmaf(dv, acc[abase + 1], bvec[colbase + 1]), 0.f);
    float o2 = fmaxf(fmaf(dv, acc[abase + 2], bvec[colbase + 2]), 0.f);
    float o3 = fmaxf(fmaf(dv, acc[abase + 3], bvec[colbase + 3]), 0.f);
    __nv_bfloat162 p0 = __floats2bfloat162_rn(o0, o1);
    __nv_bfloat162 p1 = __floats2bfloat162_rn(o2, o3);
    uint2 u = make_uint2(*(unsigned*)&p0, *(unsigned*)&p1);
    *(uint2*)(g_xb + (size_t)node * DD + colbase) = u;
}

// ---------------- pool ------------------------------------------------------
__global__ void pool_kernel() {
    __shared__ float s_acc[512];
    int g = blockIdx.x;
    int t = threadIdx.x;              // 256 threads
    int pr = t & 63;
    int q  = t >> 6;
    int n0 = g_gstart[g], n1 = g_gstart[g + 1];
    float a0 = 0.f, a1 = 0.f;
    for (int n = n0 + q; n < n1; n += 4) {
        __nv_bfloat162 v = *(const __nv_bfloat162*)(g_xb + (size_t)n * DD + pr * 2);
        float2 f = __bfloat1622float2(v);
        a0 += f.x; a1 += f.y;
    }
    s_acc[t * 2]     = a0;
    s_acc[t * 2 + 1] = a1;
    __syncthreads();
    if (t < 128) {
        int pi = t >> 1, c = t & 1;
        float s = s_acc[(0 * 64 + pi) * 2 + c] + s_acc[(1 * 64 + pi) * 2 + c] +
                  s_acc[(2 * 64 + pi) * 2 + c] + s_acc[(3 * 64 + pi) * 2 + c];
        g_pool[g * DD + pi * 2 + c] = s;
    }
}

// ---------------- final FC --------------------------------------------------
__global__ void fc_kernel(const float* Wfc, const float* bfc, float* out) {
    int g = blockIdx.x;
    int o = threadIdx.x;
    float inv = 1.0f / fmaxf((float)g_cnti[g], 1.0f);
    float acc = 0.f;
#pragma unroll 8
    for (int k = 0; k < DD; k++)
        acc = fmaf(g_pool[g * DD + k], Wfc[k * DOUT + o], acc);
    out[g * DOUT + o] = acc * inv + bfc[o];
}

// Eager init: context, smem attrs, side stream + events (pre-created, so
// kernel_launch itself performs no resource creation).
namespace {
cudaStream_t g_s2 = nullptr;
cudaEvent_t  g_ev_fork = nullptr, g_ev_join = nullptr;
struct EagerInit {
    EagerInit() {
        void* p = nullptr;
        (void)cudaGetSymbolAddress(&p, g_hb);
        (void)cudaFuncSetAttribute(gemm_mma_kernel<0>,
            cudaFuncAttributeMaxDynamicSharedMemorySize, SMEMB);
        (void)cudaFuncSetAttribute(gemm_mma_kernel<1>,
            cudaFuncAttributeMaxDynamicSharedMemorySize, SMEMB);
        (void)cudaStreamCreateWithFlags(&g_s2, cudaStreamNonBlocking);
        (void)cudaEventCreateWithFlags(&g_ev_fork, cudaEventDisableTiming);
        (void)cudaEventCreateWithFlags(&g_ev_join, cudaEventDisableTiming);
    }
};
EagerInit eager_init_instance;
}

// ---------------- launch ----------------------------------------------------
extern "C" void kernel_launch(void* const* d_in, const int* in_sizes, int n_in,
                              void* d_out, int out_size) {
    const float* x     = (const float*)d_in[0];
    const int*   ei    = (const int*)d_in[1];     // int32 (JAX x64 disabled)
    const int*   batch = (const int*)d_in[2];     // int32
    const float* W1  = (const float*)d_in[3];
    const float* b1  = (const float*)d_in[4];
    const float* W2  = (const float*)d_in[5];
    const float* b2  = (const float*)d_in[6];
    const float* W3  = (const float*)d_in[7];
    const float* b3  = (const float*)d_in[8];
    const float* Wfc = (const float*)d_in[9];
    const float* bfc = (const float*)d_in[10];
    float* out = (float*)d_out;

    const int* srcp = ei;
    const int* dstp = ei + NE;

    // fork: edge/graph prep on side stream, concurrent with wprep+GEMM1
    cudaEventRecord(g_ev_fork, 0);
    cudaStreamWaitEvent(g_s2, g_ev_fork, 0);

    init_kernel<<<(NN + 255) / 256, 256, 0, g_s2>>>();
    deg_kernel<<<(NE / 4 + 255) / 256, 256, 0, g_s2>>>(dstp);
    node_kernel<<<(NN + 255) / 256, 256, 0, g_s2>>>(batch);
    scanA_kernel<<<NBLK, 128, 0, g_s2>>>();
    scanB_kernel<<<1, 128, 0, g_s2>>>();
    scanC_kernel<<<NBLK, 128, 0, g_s2>>>();
    place_kernel<<<(NE + 255) / 256, 256, 0, g_s2>>>(srcp, dstp);
    cudaEventRecord(g_ev_join, g_s2);

    // main stream: weight images + graph-independent GEMM1
    wprep_kernel<<<64, 256>>>(W1, 0);
    wprep_kernel<<<64, 256>>>(W2, 1);
    wprep_kernel<<<64, 256>>>(W3, 2);
    gemm_mma_kernel<0><<<NTILE, 256, SMEMB>>>(x, 0);

    // join: gathers need CSR + dinv
    cudaStreamWaitEvent(0, g_ev_join, 0);

    gather_kernel<<<(NN + 7) / 8, 256>>>(b1);
    gemm_mma_kernel<1><<<NTILE, 256, SMEMB>>>(nullptr, 1);
    gather_kernel<<<(NN + 7) / 8, 256>>>(b2);
    gemm_mma_kernel<1><<<NTILE, 256, SMEMB>>>(nullptr, 2);
    gather_kernel<<<(NN + 7) / 8, 256>>>(b3);

    pool_kernel<<<NG, 256>>>();
    fc_kernel<<<NG, DOUT>>>(Wfc, bfc, out);
}

// round 17
// speedup vs baseline: 1.1969x; 1.1969x over previous
#include <cuda_runtime.h>
#include <cuda_bf16.h>
#include <cstdint>

#define NN    100000
#define NE    1600000
#define DD    128
#define NG    128
#define DOUT  64
#define NBLK  98          // ceil(NN / 1024)
#define NTILE 782         // ceil(NN / 128)

#define APAD  8
#define AK    (DD + APAD)                    // 136 bf16 per row
#define SMEMB (3 * 128 * AK * 2)             // As + Bh + Bl = 104448 B

// ---------------- scratch (device globals: allocation-free) ----------------
__device__ __align__(16) __nv_bfloat16 g_hb[(size_t)NN * DD]; // h' = (xW)*dinv, bf16
__device__ __align__(16) __nv_bfloat16 g_xb[(size_t)NN * DD]; // layer output, bf16
__device__ __align__(16) __nv_bfloat16 g_wsw[3 * 32768];      // W^T split hi+lo
__device__ float g_dinv[NN];
__device__ int   g_indeg[NN];
__device__ int   g_off  [NN];
__device__ int   g_cur  [NN];
__device__ int   g_srcl [NE];
__device__ int   g_bsum [NBLK];
__device__ int   g_bbase[NBLK];
__device__ int   g_cnti [NG];
__device__ int   g_gstart[NG + 1];

// ---------------- mma/ldmatrix helpers --------------------------------------
__device__ __forceinline__ uint32_t smem_u32(const void* p) {
    uint32_t a;
    asm("{ .reg .u64 t; cvta.to.shared.u64 t, %1; cvt.u32.u64 %0, t; }"
        : "=r"(a) : "l"(p));
    return a;
}
__device__ __forceinline__ void ldsm_x4(uint32_t (&r)[4], uint32_t addr) {
    asm volatile("ldmatrix.sync.aligned.m8n8.x4.shared.b16 {%0,%1,%2,%3}, [%4];"
                 : "=r"(r[0]), "=r"(r[1]), "=r"(r[2]), "=r"(r[3]) : "r"(addr));
}
__device__ __forceinline__ void mma_16816(float (&c)[4], const uint32_t (&a)[4],
                                          uint32_t b0, uint32_t b1) {
    asm volatile("mma.sync.aligned.m16n8k16.row.col.f32.bf16.bf16.f32 "
                 "{%0,%1,%2,%3}, {%4,%5,%6,%7}, {%8,%9}, {%0,%1,%2,%3};"
                 : "+f"(c[0]), "+f"(c[1]), "+f"(c[2]), "+f"(c[3])
                 : "r"(a[0]), "r"(a[1]), "r"(a[2]), "r"(a[3]), "r"(b0), "r"(b1));
}

// ---------------- init ------------------------------------------------------
__global__ void init_kernel() {
    int i = blockIdx.x * blockDim.x + threadIdx.x;
    if (i < NN) { g_indeg[i] = 0; g_cur[i] = 0; }
    if (i < NG) g_cnti[i] = 0;
}

// ---------------- in-degree histogram over dst (int4) -----------------------
__global__ void deg_kernel(const int* dst) {
    int i = blockIdx.x * blockDim.x + threadIdx.x;
    if (i < NE / 4) {
        int4 d4 = ((const int4*)dst)[i];
        if ((unsigned)d4.x < NN) atomicAdd(&g_indeg[d4.x], 1);
        if ((unsigned)d4.y < NN) atomicAdd(&g_indeg[d4.y], 1);
        if ((unsigned)d4.z < NN) atomicAdd(&g_indeg[d4.z], 1);
        if ((unsigned)d4.w < NN) atomicAdd(&g_indeg[d4.w], 1);
    }
}

// ------- fused scanA + node: dinv, per-graph counts, block sums -------------
__global__ void scanA_node_kernel(const int* batch) {
    __shared__ int sh[128];
    int b = blockIdx.x, t = threadIdx.x;
    int base = b * 1024 + t * 8;
    int s = 0;
    int curg = -1, run = 0;
#pragma unroll
    for (int j = 0; j < 8; j++) {
        int idx = base + j;
        if (idx < NN) {
            int dg = g_indeg[idx];
            s += dg;
            g_dinv[idx] = rsqrtf(1.0f + (float)dg);
            int bg = batch[idx];
            if ((unsigned)bg < NG) {
                if (bg == curg) run++;
                else {
                    if (run > 0) atomicAdd(&g_cnti[curg], run);
                    curg = bg; run = 1;
                }
            }
        }
    }
    if (run > 0) atomicAdd(&g_cnti[curg], run);
    sh[t] = s;
    __syncthreads();
    for (int off = 64; off > 0; off >>= 1) {
        if (t < off) sh[t] += sh[t + off];
        __syncthreads();
    }
    if (t == 0) g_bsum[b] = sh[0];
}

// ---------------- scan B ----------------------------------------------------
__global__ void scanB_kernel() {
    __shared__ int ts[128];
    int t = threadIdx.x;
    int v = (t < NBLK) ? g_bsum[t] : 0;
    ts[t] = v;
    __syncthreads();
    for (int off = 1; off < 128; off <<= 1) {
        int xv = (t >= off) ? ts[t - off] : 0;
        __syncthreads();
        ts[t] += xv;
        __syncthreads();
    }
    if (t < NBLK) g_bbase[t] = ts[t] - v;
    __syncthreads();
    int c = g_cnti[t];
    ts[t] = c;
    __syncthreads();
    for (int off = 1; off < 128; off <<= 1) {
        int xv = (t >= off) ? ts[t - off] : 0;
        __syncthreads();
        ts[t] += xv;
        __syncthreads();
    }
    g_gstart[t] = ts[t] - c;
    if (t == 127) g_gstart[128] = ts[127];
}

// ---------------- scan C ----------------------------------------------------
__global__ void scanC_kernel() {
    __shared__ int ts[128];
    int b = blockIdx.x, t = threadIdx.x;
    int base = b * 1024 + t * 8;
    int e[8];
    int s = 0;
#pragma unroll
    for (int j = 0; j < 8; j++) {
        int idx = base + j;
        int v = (idx < NN) ? g_indeg[idx] : 0;
        e[j] = s;
        s += v;
    }
    ts[t] = s;
    __syncthreads();
    for (int off = 1; off < 128; off <<= 1) {
        int xv = (t >= off) ? ts[t - off] : 0;
        __syncthreads();
        ts[t] += xv;
        __syncthreads();
    }
    int tbase = g_bbase[b] + (t > 0 ? ts[t - 1] : 0);
#pragma unroll
    for (int j = 0; j < 8; j++) {
        int idx = base + j;
        if (idx < NN) g_off[idx] = tbase + e[j];
    }
}

// ---------------- placement -------------------------------------------------
__global__ void place_kernel(const int* src, const int* dst) {
    int e = blockIdx.x * blockDim.x + threadIdx.x;
    if (e >= NE) return;
    unsigned d = (unsigned)dst[e];
    unsigned s = (unsigned)src[e];
    if (d < NN && s < NN) {
        int p = g_off[d] + atomicAdd(&g_cur[d], 1);
        g_srcl[p] = (int)s;
    }
}

// ---------------- W prep: all 3 layers in one launch ------------------------
__global__ void wprep_all_kernel(const float* W1, const float* W2,
                                 const float* W3) {
    int gid = blockIdx.x * blockDim.x + threadIdx.x;   // 3*16384
    if (gid >= 3 * 16384) return;
    int layer = gid >> 14;
    int id = gid & 16383;
    const float* W = (layer == 0) ? W1 : (layer == 1) ? W2 : W3;
    int k = id & 127, n = id >> 7;
    float w = W[(size_t)k * DD + n];
    __nv_bfloat16 hi = __float2bfloat16(w);
    __nv_bfloat16 lo = __float2bfloat16(w - __bfloat162float(hi));
    g_wsw[layer * 32768 + id]         = hi;
    g_wsw[layer * 32768 + 16384 + id] = lo;
}

// ---------------- mma.sync GEMM: h' = bf16((A @ W) * dinv[row]) -------------
template <int USE_GX>
__global__ __launch_bounds__(256)
void gemm_mma_kernel(const float* A_ext, int layer) {
    extern __shared__ char smc[];
    __nv_bfloat16* As = (__nv_bfloat16*)smc;            // [128][AK]

    int t = threadIdx.x;
    int lane = t & 31, wid = t >> 5;
    int warp_m = wid & 3, warp_n = wid >> 2;
    int base = blockIdx.x * 128;

    // ---- stage A tile ----
    if (USE_GX) {
#pragma unroll
        for (int it = 0; it < 8; it++) {
            int j = it * 256 + t;          // 2048 uint4
            int row = j >> 4, seg = j & 15;
            int grow = base + row;
            uint4 v = make_uint4(0, 0, 0, 0);
            if (grow < NN)
                v = *(const uint4*)(g_xb + (size_t)grow * DD + seg * 8);
            *(uint4*)&As[row * AK + seg * 8] = v;
        }
    } else {
#pragma unroll
        for (int it = 0; it < 16; it++) {
            int j = it * 256 + t;          // 4096 float4
            int row = j >> 5, c4 = j & 31;
            int grow = base + row;
            float4 v = make_float4(0.f, 0.f, 0.f, 0.f);
            if (grow < NN)
                v = *(const float4*)(A_ext + (size_t)grow * DD + c4 * 4);
            __nv_bfloat162 p0 = __floats2bfloat162_rn(v.x, v.y);
            __nv_bfloat162 p1 = __floats2bfloat162_rn(v.z, v.w);
            uint2 u = make_uint2(*(unsigned*)&p0, *(unsigned*)&p1);
            *(uint2*)&As[row * AK + c4 * 4] = u;
        }
    }
    // ---- stage B tiles ----
    {
        const uint4* wsrc = (const uint4*)(g_wsw + layer * 32768);
#pragma unroll
        for (int it = 0; it < 16; it++) {
            int j = it * 256 + t;          // 4096 uint4 over both parts
            int part = j >> 11;
            int idx = j & 2047;
            int n = idx >> 4, seg = idx & 15;
            uint4 v = wsrc[j];
            __nv_bfloat16* Bp = As + 128 * AK + part * 128 * AK;
            *(uint4*)&Bp[n * AK + seg * 8] = v;
        }
    }
    __syncthreads();

    // ---- mainloop: 8 k-steps x (hi, lo) ----
    float acc[2][8][4];
#pragma unroll
    for (int i = 0; i < 2; i++)
#pragma unroll
        for (int j = 0; j < 8; j++)
#pragma unroll
            for (int q = 0; q < 4; q++) acc[i][j][q] = 0.f;

    uint32_t smb = smem_u32(As);
#pragma unroll
    for (int ks = 0; ks < 8; ks++) {
        uint32_t a[2][4];
#pragma unroll
        for (int i = 0; i < 2; i++) {
            int row = warp_m * 32 + i * 16 + (lane & 15);
            int kof = ks * 16 + (lane >> 4) * 8;
            ldsm_x4(a[i], smb + (row * AK + kof) * 2);
        }
#pragma unroll
        for (int part = 0; part < 2; part++) {
            uint32_t boff = (uint32_t)((128 * AK + part * 128 * AK) * 2);
#pragma unroll
            for (int j2 = 0; j2 < 4; j2++) {
                uint32_t b[4];
                int g = lane >> 3;
                int n = warp_n * 64 + j2 * 16 + (g >> 1) * 8 + (lane & 7);
                int kof = ks * 16 + (g & 1) * 8;
                ldsm_x4(b, smb + boff + (n * AK + kof) * 2);
#pragma unroll
                for (int i = 0; i < 2; i++) {
                    mma_16816(acc[i][2 * j2 + 0], a[i], b[0], b[1]);
                    mma_16816(acc[i][2 * j2 + 1], a[i], b[2], b[3]);
                }
            }
        }
    }

    // ---- epilogue: scale by dinv, pack bf16x2, store ----
#pragma unroll
    for (int i = 0; i < 2; i++) {
        int r0 = base + warp_m * 32 + i * 16 + (lane >> 2);
        int r1 = r0 + 8;
        float dv0 = (r0 < NN) ? g_dinv[r0] : 0.f;
        float dv1 = (r1 < NN) ? g_dinv[r1] : 0.f;
#pragma unroll
        for (int j = 0; j < 8; j++) {
            int col = warp_n * 64 + j * 8 + (lane & 3) * 2;
            if (r0 < NN) {
                __nv_bfloat162 p = __floats2bfloat162_rn(acc[i][j][0] * dv0,
                                                         acc[i][j][1] * dv0);
                *(unsigned*)(g_hb + (size_t)r0 * DD + col) = *(unsigned*)&p;
            }
            if (r1 < NN) {
                __nv_bfloat162 p = __floats2bfloat162_rn(acc[i][j][2] * dv1,
                                                         acc[i][j][3] * dv1);
                *(unsigned*)(g_hb + (size_t)r1 * DD + col) = *(unsigned*)&p;
            }
        }
    }
}

// ---------------- gather: xb[d] = bf16(relu(dinv[d]*(h'[d]+Σh'[s])+b)) ------
__global__ void gather_kernel(const float* bvec) {
    __shared__ int s_idx[8][32];
    int warp = threadIdx.x >> 5, lane = threadIdx.x & 31;
    int node = blockIdx.x * 8 + warp;
    if (node >= NN) return;

    int start = g_off[node];
    int cnt   = g_indeg[node];
    int half  = lane >> 4;
    int l16   = lane & 15;

    float acc[8];
#pragma unroll
    for (int k = 0; k < 8; k++) acc[k] = 0.0f;

    if (half == 0) {
        uint4 v = *(const uint4*)(g_hb + (size_t)node * DD + l16 * 8);
        float2 f0 = __bfloat1622float2(*(__nv_bfloat162*)&v.x);
        float2 f1 = __bfloat1622float2(*(__nv_bfloat162*)&v.y);
        float2 f2 = __bfloat1622float2(*(__nv_bfloat162*)&v.z);
        float2 f3 = __bfloat1622float2(*(__nv_bfloat162*)&v.w);
        acc[0] = f0.x; acc[1] = f0.y; acc[2] = f1.x; acc[3] = f1.y;
        acc[4] = f2.x; acc[5] = f2.y; acc[6] = f3.x; acc[7] = f3.y;
    }

    for (int c = 0; c < cnt; c += 32) {
        int rem = cnt - c;
        if (rem > 32) rem = 32;
        if (lane < rem) s_idx[warp][lane] = g_srcl[start + c + lane];
        __syncwarp();
#pragma unroll 4
        for (int j = half; j < rem; j += 2) {
            int s = s_idx[warp][j];
            uint4 v = *(const uint4*)(g_hb + (size_t)s * DD + l16 * 8);
            float2 f0 = __bfloat1622float2(*(__nv_bfloat162*)&v.x);
            float2 f1 = __bfloat1622float2(*(__nv_bfloat162*)&v.y);
            float2 f2 = __bfloat1622float2(*(__nv_bfloat162*)&v.z);
            float2 f3 = __bfloat1622float2(*(__nv_bfloat162*)&v.w);
            acc[0] += f0.x; acc[1] += f0.y; acc[2] += f1.x; acc[3] += f1.y;
            acc[4] += f2.x; acc[5] += f2.y; acc[6] += f3.x; acc[7] += f3.y;
        }
        __syncwarp();
    }

#pragma unroll
    for (int k = 0; k < 8; k++)
        acc[k] += __shfl_xor_sync(0xffffffffu, acc[k], 16);

    float dv = g_dinv[node];
    int colbase = l16 * 8 + half * 4;
    int abase = half * 4;
    float o0 = fmaxf(fmaf(dv, acc[abase + 0], bvec[colbase + 0]), 0.f);
    float o1 = fmaxf(fmaf(dv, acc[abase + 1], bvec[colbase + 1]), 0.f);
    float o2 = fmaxf(fmaf(dv, acc[abase + 2], bvec[colbase + 2]), 0.f);
    float o3 = fmaxf(fmaf(dv, acc[abase + 3], bvec[colbase + 3]), 0.f);
    __nv_bfloat162 p0 = __floats2bfloat162_rn(o0, o1);
    __nv_bfloat162 p1 = __floats2bfloat162_rn(o2, o3);
    uint2 u = make_uint2(*(unsigned*)&p0, *(unsigned*)&p1);
    *(uint2*)(g_xb + (size_t)node * DD + colbase) = u;
}

// ---------------- fused pool + FC: one block per graph ----------------------
__global__ void poolfc_kernel(const float* Wfc, const float* bfc, float* out) {
    __shared__ float s_acc[512];
    __shared__ float s_pool[DD];
    int g = blockIdx.x;
    int t = threadIdx.x;              // 256 threads
    int pr = t & 63;                  // bf16x2 pair (64 pairs = 128 feats)
    int q  = t >> 6;                  // 0..3 node interleave
    int n0 = g_gstart[g], n1 = g_gstart[g + 1];
    float a0 = 0.f, a1 = 0.f;
    for (int n = n0 + q; n < n1; n += 4) {
        __nv_bfloat162 v = *(const __nv_bfloat162*)(g_xb + (size_t)n * DD + pr * 2);
        float2 f = __bfloat1622float2(v);
        a0 += f.x; a1 += f.y;
    }
    s_acc[t * 2]     = a0;
    s_acc[t * 2 + 1] = a1;
    __syncthreads();
    if (t < 128) {
        int pi = t >> 1, c = t & 1;
        s_pool[pi * 2 + c] =
            s_acc[(0 * 64 + pi) * 2 + c] + s_acc[(1 * 64 + pi) * 2 + c] +
            s_acc[(2 * 64 + pi) * 2 + c] + s_acc[(3 * 64 + pi) * 2 + c];
    }
    __syncthreads();
    if (t < DOUT) {
        float inv = 1.0f / fmaxf((float)(n1 - n0), 1.0f);
        float acc = 0.f;
#pragma unroll 8
        for (int k = 0; k < DD; k++)
            acc = fmaf(s_pool[k], Wfc[k * DOUT + t], acc);
        out[g * DOUT + t] = acc * inv + bfc[t];
    }
}

// Eager context/module init + smem attribute before harness bookkeeping.
namespace {
struct EagerInit {
    EagerInit() {
        void* p = nullptr;
        (void)cudaGetSymbolAddress(&p, g_hb);
        (void)cudaFuncSetAttribute(gemm_mma_kernel<0>,
            cudaFuncAttributeMaxDynamicSharedMemorySize, SMEMB);
        (void)cudaFuncSetAttribute(gemm_mma_kernel<1>,
            cudaFuncAttributeMaxDynamicSharedMemorySize, SMEMB);
    }
};
EagerInit eager_init_instance;
}

// ---------------- launch ----------------------------------------------------
extern "C" void kernel_launch(void* const* d_in, const int* in_sizes, int n_in,
                              void* d_out, int out_size) {
    const float* x     = (const float*)d_in[0];
    const int*   ei    = (const int*)d_in[1];     // int32 (JAX x64 disabled)
    const int*   batch = (const int*)d_in[2];     // int32
    const float* W1  = (const float*)d_in[3];
    const float* b1  = (const float*)d_in[4];
    const float* W2  = (const float*)d_in[5];
    const float* b2  = (const float*)d_in[6];
    const float* W3  = (const float*)d_in[7];
    const float* b3  = (const float*)d_in[8];
    const float* Wfc = (const float*)d_in[9];
    const float* bfc = (const float*)d_in[10];
    float* out = (float*)d_out;

    const int* srcp = ei;
    const int* dstp = ei + NE;

    init_kernel<<<(NN + 255) / 256, 256>>>();
    wprep_all_kernel<<<192, 256>>>(W1, W2, W3);
    deg_kernel<<<(NE / 4 + 255) / 256, 256>>>(dstp);
    scanA_node_kernel<<<NBLK, 128>>>(batch);
    scanB_kernel<<<1, 128>>>();
    scanC_kernel<<<NBLK, 128>>>();
    place_kernel<<<(NE + 255) / 256, 256>>>(srcp, dstp);

    gemm_mma_kernel<0><<<NTILE, 256, SMEMB>>>(x, 0);
    gather_kernel<<<(NN + 7) / 8, 256>>>(b1);
    gemm_mma_kernel<1><<<NTILE, 256, SMEMB>>>(nullptr, 1);
    gather_kernel<<<(NN + 7) / 8, 256>>>(b2);
    gemm_mma_kernel<1><<<NTILE, 256, SMEMB>>>(nullptr, 2);
    gather_kernel<<<(NN + 7) / 8, 256>>>(b3);

    poolfc_kernel<<<NG, 256>>>(Wfc, bfc, out);
}